// round 10
// baseline (speedup 1.0000x reference)
#include <cuda_runtime.h>
#include <cuda_bf16.h>
#include <math.h>
#include <stdint.h>

#define BATCH 16
#define CH    256
#define NPIX  4096
#define CN    (CH * NPIX)

typedef __nv_bfloat16 bf16;

// ---------------- device-global scratch (allocation-free) ----------------
__device__ float g_inv1[BATCH * CH];
__device__ float g_inv2[BATCH * CH];
__device__ __align__(16) bf16 g_s [BATCH * CN];   // inv1*x1+inv2*x2 [b][c][n]
__device__ __align__(16) bf16 g_r1[BATCH * CN];   // raw bf16 x1     [b][c][n]
__device__ __align__(16) bf16 g_r2[BATCH * CN];   // raw bf16 x2     [b][c][n]
__device__ __align__(16) float g_Sp[4][BATCH * CH * CH]; // partials [mat*2+ks]
__device__ __align__(16) bf16 g_A1[BATCH * CH * CH];     // bf16 probs
__device__ __align__(16) bf16 g_A2[BATCH * CH * CH];

// ---------------- PTX helpers ----------------
__device__ __forceinline__ uint32_t smem_u32(const void* p) {
    uint32_t a;
    asm("{ .reg .u64 t; cvta.to.shared.u64 t, %1; cvt.u32.u64 %0, t; }" : "=r"(a) : "l"(p));
    return a;
}
__device__ __forceinline__ void cpasync16(uint32_t s, const void* g) {
    asm volatile("cp.async.cg.shared.global [%0], [%1], 16;" :: "r"(s), "l"(g));
}
#define CP_COMMIT() asm volatile("cp.async.commit_group;")
#define CP_WAIT(N)  asm volatile("cp.async.wait_group %0;" :: "n"(N))

__device__ __forceinline__ void ldm_x4(uint32_t* r, uint32_t a) {
    asm volatile("ldmatrix.sync.aligned.m8n8.x4.shared.b16 {%0,%1,%2,%3}, [%4];"
        : "=r"(r[0]), "=r"(r[1]), "=r"(r[2]), "=r"(r[3]) : "r"(a));
}
__device__ __forceinline__ void ldm_x4t(uint32_t* r, uint32_t a) {
    asm volatile("ldmatrix.sync.aligned.m8n8.x4.trans.shared.b16 {%0,%1,%2,%3}, [%4];"
        : "=r"(r[0]), "=r"(r[1]), "=r"(r[2]), "=r"(r[3]) : "r"(a));
}
__device__ __forceinline__ void mma16816(float* c, const uint32_t* a, const uint32_t* b) {
    asm volatile("mma.sync.aligned.m16n8k16.row.col.f32.bf16.bf16.f32 "
        "{%0,%1,%2,%3}, {%4,%5,%6,%7}, {%8,%9}, {%0,%1,%2,%3};"
        : "+f"(c[0]), "+f"(c[1]), "+f"(c[2]), "+f"(c[3])
        : "r"(a[0]), "r"(a[1]), "r"(a[2]), "r"(a[3]), "r"(b[0]), "r"(b[1]));
}

// Row-major operand tiles: pitch 80 B for [rows][32k] bf16 tiles.
#define ROW_B    80
#define ATILE_B  (128 * ROW_B)       // 10240 B (A: 128 rows)
#define PIPE     4
// gram: B tile 256 rows x 32 k  -> 20480 B
#define GBTILE_B (256 * ROW_B)
#define GSTAGE_B (ATILE_B + GBTILE_B)   // 30720
#define SM_GRAM  (PIPE * GSTAGE_B)      // 122880
// out:  B tile [32 k][256 n], pitch 528 B (33x16B, conflict-free)
#define BROW_B   528
#define OBTILE_B (32 * BROW_B)          // 16896
#define OSTAGE_B (ATILE_B + OBTILE_B)   // 27136
#define SM_OUT   (PIPE * OSTAGE_B)      // 108544

// ---------------------------------------------------------------------------
// Stage fills (512 threads)
// ---------------------------------------------------------------------------
__device__ __forceinline__ void fill_gram(const bf16* __restrict__ Ag, int lda,
                                          const bf16* __restrict__ Bg, int ldb,
                                          int k0, uint32_t st, int t) {
    const int r  = t >> 2;            // 0..127
    const int cb = (t & 3);           // 16B chunk
    cpasync16(st + r * ROW_B + cb * 16, Ag + (size_t)r * lda + k0 + cb * 8);
    const uint32_t sb = st + ATILE_B;
    cpasync16(sb + r * ROW_B + cb * 16, Bg + (size_t)r * ldb + k0 + cb * 8);
    cpasync16(sb + (r + 128) * ROW_B + cb * 16,
              Bg + (size_t)(r + 128) * ldb + k0 + cb * 8);
}

__device__ __forceinline__ void fill_tb(const bf16* __restrict__ Ag, int lda,
                                        const bf16* __restrict__ Bg, int ldb,
                                        int k0, uint32_t st, int t) {
    const int r  = t >> 2;
    const int cb = (t & 3);
    cpasync16(st + r * ROW_B + cb * 16, Ag + (size_t)r * lda + k0 + cb * 8);
    const uint32_t sb = st + ATILE_B;
    const int br = t >> 5;            // 0..15
    const int bc = t & 31;            // 16B chunk along n (256n*2B = 32 chunks)
    cpasync16(sb + br * BROW_B + bc * 16, Bg + (size_t)(k0 + br) * ldb + bc * 8);
    cpasync16(sb + (br + 16) * BROW_B + bc * 16,
              Bg + (size_t)(k0 + br + 16) * ldb + bc * 8);
}

// ---------------------------------------------------------------------------
// Compute one 32-k stage. 16 warps: mw0 = (w>>3)*64, nw0 = (w&7)*32.
// ---------------------------------------------------------------------------
__device__ __forceinline__ void compute_stage(uint32_t Abase, uint32_t Bbase,
                                              int mw0, int nw0, int lA_row, int lA_k,
                                              int lB_row, int lB_k,
                                              float acc[4][4][4]) {
    #pragma unroll
    for (int ks = 0; ks < 2; ks++) {
        uint32_t afr[4][4], bfr[4][2];
        #pragma unroll
        for (int i = 0; i < 4; i++)
            ldm_x4(afr[i], Abase + (mw0 + i * 16 + lA_row) * ROW_B
                                 + (ks * 16 + lA_k) * 2);
        #pragma unroll
        for (int p = 0; p < 2; p++) {
            uint32_t r[4];
            ldm_x4(r, Bbase + (nw0 + p * 16 + lB_row) * ROW_B
                            + (ks * 16 + lB_k) * 2);
            bfr[p * 2][0] = r[0]; bfr[p * 2][1] = r[1];
            bfr[p * 2 + 1][0] = r[2]; bfr[p * 2 + 1][1] = r[3];
        }
        #pragma unroll
        for (int i = 0; i < 4; i++)
            #pragma unroll
            for (int j = 0; j < 4; j++)
                mma16816(acc[i][j], afr[i], bfr[j]);
    }
}

__device__ __forceinline__ void compute_stage_tb(uint32_t Abase, uint32_t Bbase,
                                                 int mw0, int nw0, int lA_row, int lA_k,
                                                 int q, int l,
                                                 float acc[4][4][4]) {
    #pragma unroll
    for (int ks = 0; ks < 2; ks++) {
        uint32_t afr[4][4], bfr[4][2];
        #pragma unroll
        for (int i = 0; i < 4; i++)
            ldm_x4(afr[i], Abase + (mw0 + i * 16 + lA_row) * ROW_B
                                 + (ks * 16 + lA_k) * 2);
        #pragma unroll
        for (int p = 0; p < 2; p++) {
            uint32_t r[4];
            ldm_x4t(r, Bbase + (ks * 16 + (q & 1) * 8 + (l & 7)) * BROW_B
                             + (nw0 + p * 16 + (q >> 1) * 8) * 2);
            bfr[p * 2][0] = r[0]; bfr[p * 2][1] = r[1];
            bfr[p * 2 + 1][0] = r[2]; bfr[p * 2 + 1][1] = r[3];
        }
        #pragma unroll
        for (int i = 0; i < 4; i++)
            #pragma unroll
            for (int j = 0; j < 4; j++)
                mma16816(acc[i][j], afr[i], bfr[j]);
    }
}

// ---------------------------------------------------------------------------
// Kernel 1: fused norms + bf16 conversion.
// ---------------------------------------------------------------------------
__global__ __launch_bounds__(256) void normconv_kernel(const float* __restrict__ x1,
                                                       const float* __restrict__ x2) {
    const int row = blockIdx.x;                     // b*CH + c
    const int t = threadIdx.x;
    const size_t base = (size_t)row * NPIX;
    float4 va[4], vb[4];
    float s1 = 0.f, s2 = 0.f;
    #pragma unroll
    for (int p = 0; p < 4; p++) {
        va[p] = *(const float4*)(x1 + base + (size_t)(p * 256 + t) * 4);
        vb[p] = *(const float4*)(x2 + base + (size_t)(p * 256 + t) * 4);
        s1 += va[p].x * va[p].x + va[p].y * va[p].y + va[p].z * va[p].z + va[p].w * va[p].w;
        s2 += vb[p].x * vb[p].x + vb[p].y * vb[p].y + vb[p].z * vb[p].z + vb[p].w * vb[p].w;
    }
    __shared__ float sh1[8], sh2[8];
    const int lane = t & 31, w = t >> 5;
    #pragma unroll
    for (int o = 16; o; o >>= 1) {
        s1 += __shfl_xor_sync(0xffffffffu, s1, o);
        s2 += __shfl_xor_sync(0xffffffffu, s2, o);
    }
    if (lane == 0) { sh1[w] = s1; sh2[w] = s2; }
    __syncthreads();
    float t1 = 0.f, t2 = 0.f;
    #pragma unroll
    for (int i = 0; i < 8; i++) { t1 += sh1[i]; t2 += sh2[i]; }
    const float i1 = 1.f / fmaxf(sqrtf(t1), 1e-12f);
    const float i2 = 1.f / fmaxf(sqrtf(t2), 1e-12f);
    if (t == 0) { g_inv1[row] = i1; g_inv2[row] = i2; }

    #pragma unroll
    for (int p = 0; p < 4; p++) {
        const size_t off = base + (size_t)(p * 256 + t) * 4;
        const float a[4]  = {va[p].x, va[p].y, va[p].z, va[p].w};
        const float bb[4] = {vb[p].x, vb[p].y, vb[p].z, vb[p].w};
        bf16 sv[4], r1v[4], r2v[4];
        #pragma unroll
        for (int i = 0; i < 4; i++) {
            sv[i]  = __float2bfloat16(i1 * a[i] + i2 * bb[i]);
            r1v[i] = __float2bfloat16(a[i]);
            r2v[i] = __float2bfloat16(bb[i]);
        }
        *(uint2*)(g_s  + off) = *(const uint2*)sv;
        *(uint2*)(g_r1 + off) = *(const uint2*)r1v;
        *(uint2*)(g_r2 + off) = *(const uint2*)r2v;
    }
}

// ---------------------------------------------------------------------------
// Kernel 2: gram HMMA. 512 threads, tile 128c x 256d (full d), split-K=2.
// grid (2 cblk, B*4): z = b*4 + mat*2 + ks. 128 CTAs = one wave.
// ---------------------------------------------------------------------------
__global__ __launch_bounds__(512, 1) void gram_mma() {
    extern __shared__ char sm[];
    const uint32_t smb = smem_u32(sm);
    const int t = threadIdx.x, w = t >> 5, l = t & 31;
    const int cblk = blockIdx.x;
    const int zi = blockIdx.y;
    const int b = zi >> 2, mat = (zi >> 1) & 1, ks = zi & 1;

    const bf16* Ag = g_s + (size_t)b * CN + (size_t)(cblk * 128) * NPIX + ks * 2048;
    const bf16* Bg = (mat ? g_r2 : g_r1) + (size_t)b * CN + ks * 2048;

    const int mw0 = (w >> 3) * 64, nw0 = (w & 7) * 32;
    const int lA_row = l & 15, lA_k = (l >> 4) * 8;
    const int q = l >> 3;
    const int lB_row = ((q >> 1) * 8) + (l & 7);
    const int lB_k = (q & 1) * 8;

    float acc[4][4][4] = {};
    const int niter = 2048 / 32;     // 64

    #pragma unroll
    for (int s = 0; s < PIPE - 1; s++) {
        fill_gram(Ag, NPIX, Bg, NPIX, s * 32, smb + s * GSTAGE_B, t);
        CP_COMMIT();
    }
    #pragma unroll 1
    for (int it = 0; it < niter; it++) {
        CP_WAIT(PIPE - 2);
        __syncthreads();
        if (it + PIPE - 1 < niter)
            fill_gram(Ag, NPIX, Bg, NPIX, (it + PIPE - 1) * 32,
                      smb + ((it + PIPE - 1) & (PIPE - 1)) * GSTAGE_B, t);
        CP_COMMIT();
        const uint32_t Abase = smb + (it & (PIPE - 1)) * GSTAGE_B;
        compute_stage(Abase, Abase + ATILE_B, mw0, nw0, lA_row, lA_k, lB_row, lB_k, acc);
    }

    float* S = g_Sp[mat * 2 + ks] + (size_t)(b * CH + cblk * 128) * CH;
    const int rr = l >> 2, cc = (l & 3) * 2;
    #pragma unroll
    for (int i = 0; i < 4; i++)
        #pragma unroll
        for (int j = 0; j < 4; j++) {
            const int c_ = mw0 + i * 16 + rr;
            const int d_ = nw0 + j * 8 + cc;
            float2 lo = {acc[i][j][0], acc[i][j][1]};
            float2 hi = {acc[i][j][2], acc[i][j][3]};
            *(float2*)&S[(size_t)c_ * CH + d_] = lo;
            *(float2*)&S[(size_t)(c_ + 8) * CH + d_] = hi;
        }
}

// ---------------------------------------------------------------------------
// Kernel 3: softmax. Sums split-K partials, applies inv[d], emits bf16 probs.
// ---------------------------------------------------------------------------
__global__ __launch_bounds__(256) void softmax_kernel() {
    const int row = blockIdx.x;                  // b*CH + c
    const int t = threadIdx.x;
    const int lane = t & 31, w = t >> 5;
    __shared__ float sh1[8], sh2[8];
    const size_t base = (size_t)row * CH;
    const int invb = (row >> 8) << 8;            // b*CH
    const float v1 = (g_Sp[0][base + t] + g_Sp[1][base + t]) * g_inv1[invb + t];
    const float v2 = (g_Sp[2][base + t] + g_Sp[3][base + t]) * g_inv2[invb + t];

    float m1 = v1, m2 = v2;
    #pragma unroll
    for (int o = 16; o; o >>= 1) {
        m1 = fmaxf(m1, __shfl_xor_sync(0xffffffffu, m1, o));
        m2 = fmaxf(m2, __shfl_xor_sync(0xffffffffu, m2, o));
    }
    if (lane == 0) { sh1[w] = m1; sh2[w] = m2; }
    __syncthreads();
    m1 = sh1[0]; m2 = sh2[0];
    #pragma unroll
    for (int i = 1; i < 8; i++) { m1 = fmaxf(m1, sh1[i]); m2 = fmaxf(m2, sh2[i]); }

    const float e1 = __expf(v1 - m1);
    const float e2 = __expf(v2 - m2);
    __syncthreads();

    float s1 = e1, s2 = e2;
    #pragma unroll
    for (int o = 16; o; o >>= 1) {
        s1 += __shfl_xor_sync(0xffffffffu, s1, o);
        s2 += __shfl_xor_sync(0xffffffffu, s2, o);
    }
    if (lane == 0) { sh1[w] = s1; sh2[w] = s2; }
    __syncthreads();
    s1 = 0.f; s2 = 0.f;
    #pragma unroll
    for (int i = 0; i < 8; i++) { s1 += sh1[i]; s2 += sh2[i]; }

    g_A1[base + t] = __float2bfloat16(e1 / s1);
    g_A2[base + t] = __float2bfloat16(e2 / s2);
}

// ---------------------------------------------------------------------------
// Kernel 4: back-projection HMMA (trans-B). 512 threads, tile 128c x 256n,
// fused 16-iter single-sync loop. grid (2 cblk, 16 nblk, B).
// ---------------------------------------------------------------------------
#define ZPITCH 132

__global__ __launch_bounds__(512, 1) void out_mma(const float* __restrict__ x1,
                                                  const float* __restrict__ x2,
                                                  float* __restrict__ out) {
    extern __shared__ char sm[];
    const uint32_t smb = smem_u32(sm);
    const int t = threadIdx.x, w = t >> 5, l = t & 31;
    const int cblk = blockIdx.x, nblk = blockIdx.y, b = blockIdx.z;
    const int n0 = nblk * 256, c0 = cblk * 128;

    const bf16* Apt[2] = { g_A1 + (size_t)(b * CH + c0) * CH,
                           g_A2 + (size_t)(b * CH + c0) * CH };
    const bf16* Bpt[2] = { g_r1 + (size_t)b * CN + n0,
                           g_r2 + (size_t)b * CN + n0 };

    const int mw0 = (w >> 3) * 64, nw0 = (w & 7) * 32;
    const int lA_row = l & 15, lA_k = (l >> 4) * 8;
    const int q = l >> 3;

    float acc[4][4][4] = {};
    const int niter = 16;            // 2 mats x 8 k-chunks

    #pragma unroll
    for (int s = 0; s < PIPE - 1; s++) {
        fill_tb(Apt[s >> 3], CH, Bpt[s >> 3], NPIX, (s & 7) * 32,
                smb + s * OSTAGE_B, t);
        CP_COMMIT();
    }
    #pragma unroll 1
    for (int it = 0; it < niter; it++) {
        CP_WAIT(PIPE - 2);
        __syncthreads();
        if (it + PIPE - 1 < niter) {
            const int nx = it + PIPE - 1;
            fill_tb(Apt[nx >> 3], CH, Bpt[nx >> 3], NPIX, (nx & 7) * 32,
                    smb + (nx & (PIPE - 1)) * OSTAGE_B, t);
        }
        CP_COMMIT();
        const uint32_t Abase = smb + (it & (PIPE - 1)) * OSTAGE_B;
        compute_stage_tb(Abase, Abase + ATILE_B, mw0, nw0, lA_row, lA_k, q, l, acc);
    }
    __syncthreads();

    const int rr = l >> 2, cc = (l & 3) * 2;
    float* Zs = (float*)sm;          // [64 n][ZPITCH c]

    #pragma unroll 1
    for (int h = 0; h < 4; h++) {
        if ((nw0 >> 6) == h) {
            const int nb = nw0 - h * 64;
            #pragma unroll
            for (int i = 0; i < 4; i++)
                #pragma unroll
                for (int j = 0; j < 4; j++) {
                    const int cl = mw0 + i * 16 + rr;
                    const int nl = nb + j * 8 + cc;
                    Zs[(size_t)nl * ZPITCH + cl]           = acc[i][j][0];
                    Zs[(size_t)(nl + 1) * ZPITCH + cl]     = acc[i][j][1];
                    Zs[(size_t)nl * ZPITCH + cl + 8]       = acc[i][j][2];
                    Zs[(size_t)(nl + 1) * ZPITCH + cl + 8] = acc[i][j][3];
                }
        }
        __syncthreads();
        #pragma unroll
        for (int p = 0; p < 4; p++) {
            const int idx = t + p * 512;
            const int n = idx >> 5, c4 = (idx & 31) * 4;
            const float4 z = *(const float4*)&Zs[(size_t)n * ZPITCH + c4];
            const size_t g = (size_t)b * CN + (size_t)(n0 + h * 64 + n) * CH + c0 + c4;
            const float4 a = *(const float4*)(x1 + g);
            const float4 bb = *(const float4*)(x2 + g);
            float4 o;
            o.x = z.x + a.x + bb.x; o.y = z.y + a.y + bb.y;
            o.z = z.z + a.z + bb.z; o.w = z.w + a.w + bb.w;
            *(float4*)(out + g) = o;
        }
        __syncthreads();
    }
}

// ---------------------------------------------------------------------------
extern "C" void kernel_launch(void* const* d_in, const int* in_sizes, int n_in,
                              void* d_out, int out_size) {
    (void)in_sizes; (void)n_in; (void)out_size;
    const float* x1 = (const float*)d_in[0];
    const float* x2 = (const float*)d_in[1];
    float* out = (float*)d_out;

    cudaFuncSetAttribute(gram_mma, cudaFuncAttributeMaxDynamicSharedMemorySize, SM_GRAM);
    cudaFuncSetAttribute(out_mma,  cudaFuncAttributeMaxDynamicSharedMemorySize, SM_OUT);

    normconv_kernel<<<BATCH * CH, 256>>>(x1, x2);
    gram_mma<<<dim3(2, BATCH * 4), 512, SM_GRAM>>>();
    softmax_kernel<<<BATCH * CH, 256>>>();
    out_mma<<<dim3(2, 16, BATCH), 512, SM_OUT>>>(x1, x2, out);
}

// round 12
// speedup vs baseline: 1.0303x; 1.0303x over previous
#include <cuda_runtime.h>
#include <cuda_bf16.h>
#include <math.h>
#include <stdint.h>

#define BATCH 16
#define CH    256
#define NPIX  4096
#define CN    (CH * NPIX)

typedef __nv_bfloat16 bf16;

// ---------------- device-global scratch (allocation-free) ----------------
__device__ float g_inv1[BATCH * CH];
__device__ float g_inv2[BATCH * CH];
__device__ __align__(16) bf16 g_s [BATCH * CN];   // inv1*x1+inv2*x2 [b][c][n]
__device__ __align__(16) bf16 g_r1[BATCH * CN];   // raw bf16 x1     [b][c][n]
__device__ __align__(16) bf16 g_r2[BATCH * CN];   // raw bf16 x2     [b][c][n]
__device__ __align__(16) float g_x12[BATCH * CN]; // fp32 x1+x2      [b][c][n]
__device__ __align__(16) float g_Sp[4][BATCH * CH * CH]; // partials [mat*2+ks]
__device__ __align__(16) bf16 g_A1[BATCH * CH * CH];     // bf16 probs
__device__ __align__(16) bf16 g_A2[BATCH * CH * CH];

// ---------------- PTX helpers ----------------
__device__ __forceinline__ uint32_t smem_u32(const void* p) {
    uint32_t a;
    asm("{ .reg .u64 t; cvta.to.shared.u64 t, %1; cvt.u32.u64 %0, t; }" : "=r"(a) : "l"(p));
    return a;
}
__device__ __forceinline__ void cpasync16(uint32_t s, const void* g) {
    asm volatile("cp.async.cg.shared.global [%0], [%1], 16;" :: "r"(s), "l"(g));
}
#define CP_COMMIT() asm volatile("cp.async.commit_group;")
#define CP_WAIT(N)  asm volatile("cp.async.wait_group %0;" :: "n"(N))

__device__ __forceinline__ void ldm_x4(uint32_t* r, uint32_t a) {
    asm volatile("ldmatrix.sync.aligned.m8n8.x4.shared.b16 {%0,%1,%2,%3}, [%4];"
        : "=r"(r[0]), "=r"(r[1]), "=r"(r[2]), "=r"(r[3]) : "r"(a));
}
__device__ __forceinline__ void ldm_x4t(uint32_t* r, uint32_t a) {
    asm volatile("ldmatrix.sync.aligned.m8n8.x4.trans.shared.b16 {%0,%1,%2,%3}, [%4];"
        : "=r"(r[0]), "=r"(r[1]), "=r"(r[2]), "=r"(r[3]) : "r"(a));
}
__device__ __forceinline__ void mma16816(float* c, const uint32_t* a, const uint32_t* b) {
    asm volatile("mma.sync.aligned.m16n8k16.row.col.f32.bf16.bf16.f32 "
        "{%0,%1,%2,%3}, {%4,%5,%6,%7}, {%8,%9}, {%0,%1,%2,%3};"
        : "+f"(c[0]), "+f"(c[1]), "+f"(c[2]), "+f"(c[3])
        : "r"(a[0]), "r"(a[1]), "r"(a[2]), "r"(a[3]), "r"(b[0]), "r"(b[1]));
}

// A/B tiles 128 rows x 32 bf16, padded row = 80 B.
#define ROW_B   80
#define TILE_B  (128 * ROW_B)        // 10240 B
#define STAGE_B (2 * TILE_B)         // 20480 B
#define PIPE    4
#define SM_MAIN (PIPE * STAGE_B)     // 81920 B
// out-kernel B tile: [32 k][128 n] bf16, pitch 272 B (17x16B, conflict-free)
#define BROW_B   272
#define BTILE_B  (32 * BROW_B)       // 8704 B
#define OSTAGE_B (TILE_B + BTILE_B)  // 18944 B
#define SM_OUT   (PIPE * OSTAGE_B)   // 75776 B

// ---------------------------------------------------------------------------
// Stage fills
// ---------------------------------------------------------------------------
__device__ __forceinline__ void fill_gram(const bf16* __restrict__ Ag, int lda,
                                          const bf16* __restrict__ Bg, int ldb,
                                          int k0, uint32_t st,
                                          int fr, int fkB, int fkE) {
    const bf16* ga = Ag + (size_t)fr * lda + k0 + fkE;
    const bf16* gb = Bg + (size_t)fr * ldb + k0 + fkE;
    const uint32_t sa = st + fr * ROW_B + fkB;
    const uint32_t sb = st + TILE_B + fr * ROW_B + fkB;
    cpasync16(sa, ga);
    cpasync16(sa + 64 * ROW_B, ga + (size_t)64 * lda);
    cpasync16(sb, gb);
    cpasync16(sb + 64 * ROW_B, gb + (size_t)64 * ldb);
}

__device__ __forceinline__ void fill_tb(const bf16* __restrict__ Ag, int lda,
                                        const bf16* __restrict__ Bg, int ldb,
                                        int k0, uint32_t st,
                                        int fr, int fkB, int fkE,
                                        int br0, int bc0) {
    const bf16* ga = Ag + (size_t)fr * lda + k0 + fkE;
    const uint32_t sa = st + fr * ROW_B + fkB;
    cpasync16(sa, ga);
    cpasync16(sa + 64 * ROW_B, ga + (size_t)64 * lda);
    const uint32_t sbb = st + TILE_B;
    cpasync16(sbb + br0 * BROW_B + bc0 * 16,
              Bg + (size_t)(k0 + br0) * ldb + bc0 * 8);
    cpasync16(sbb + (br0 + 16) * BROW_B + bc0 * 16,
              Bg + (size_t)(k0 + br0 + 16) * ldb + bc0 * 8);
}

// ---------------------------------------------------------------------------
// Compute one 32-k stage.
// ---------------------------------------------------------------------------
__device__ __forceinline__ void compute_stage(uint32_t Abase, uint32_t Bbase,
                                              int mw0, int nw0, int lA_row, int lA_k,
                                              int lB_row, int lB_k,
                                              float acc[4][4][4]) {
    #pragma unroll
    for (int ks = 0; ks < 2; ks++) {
        uint32_t afr[4][4], bfr[4][2];
        #pragma unroll
        for (int i = 0; i < 4; i++)
            ldm_x4(afr[i], Abase + (mw0 + i * 16 + lA_row) * ROW_B
                                 + (ks * 16 + lA_k) * 2);
        #pragma unroll
        for (int p = 0; p < 2; p++) {
            uint32_t r[4];
            ldm_x4(r, Bbase + (nw0 + p * 16 + lB_row) * ROW_B
                            + (ks * 16 + lB_k) * 2);
            bfr[p * 2][0] = r[0]; bfr[p * 2][1] = r[1];
            bfr[p * 2 + 1][0] = r[2]; bfr[p * 2 + 1][1] = r[3];
        }
        #pragma unroll
        for (int i = 0; i < 4; i++)
            #pragma unroll
            for (int j = 0; j < 4; j++)
                mma16816(acc[i][j], afr[i], bfr[j]);
    }
}

__device__ __forceinline__ void compute_stage_tb(uint32_t Abase, uint32_t Bbase,
                                                 int mw0, int nw0, int lA_row, int lA_k,
                                                 int q, int l,
                                                 float acc[4][4][4]) {
    #pragma unroll
    for (int ks = 0; ks < 2; ks++) {
        uint32_t afr[4][4], bfr[4][2];
        #pragma unroll
        for (int i = 0; i < 4; i++)
            ldm_x4(afr[i], Abase + (mw0 + i * 16 + lA_row) * ROW_B
                                 + (ks * 16 + lA_k) * 2);
        #pragma unroll
        for (int p = 0; p < 2; p++) {
            uint32_t r[4];
            ldm_x4t(r, Bbase + (ks * 16 + (q & 1) * 8 + (l & 7)) * BROW_B
                             + (nw0 + p * 16 + (q >> 1) * 8) * 2);
            bfr[p * 2][0] = r[0]; bfr[p * 2][1] = r[1];
            bfr[p * 2 + 1][0] = r[2]; bfr[p * 2 + 1][1] = r[3];
        }
        #pragma unroll
        for (int i = 0; i < 4; i++)
            #pragma unroll
            for (int j = 0; j < 4; j++)
                mma16816(acc[i][j], afr[i], bfr[j]);
    }
}

// ---------------------------------------------------------------------------
// Kernel 1: fused norms + bf16 conversion + fp32 residual precompute.
// ---------------------------------------------------------------------------
__global__ __launch_bounds__(256) void normconv_kernel(const float* __restrict__ x1,
                                                       const float* __restrict__ x2) {
    const int row = blockIdx.x;                     // b*CH + c
    const int t = threadIdx.x;
    const size_t base = (size_t)row * NPIX;
    float4 va[4], vb[4];
    float s1 = 0.f, s2 = 0.f;
    #pragma unroll
    for (int p = 0; p < 4; p++) {
        va[p] = *(const float4*)(x1 + base + (size_t)(p * 256 + t) * 4);
        vb[p] = *(const float4*)(x2 + base + (size_t)(p * 256 + t) * 4);
        s1 += va[p].x * va[p].x + va[p].y * va[p].y + va[p].z * va[p].z + va[p].w * va[p].w;
        s2 += vb[p].x * vb[p].x + vb[p].y * vb[p].y + vb[p].z * vb[p].z + vb[p].w * vb[p].w;
    }
    __shared__ float sh1[8], sh2[8];
    const int lane = t & 31, w = t >> 5;
    #pragma unroll
    for (int o = 16; o; o >>= 1) {
        s1 += __shfl_xor_sync(0xffffffffu, s1, o);
        s2 += __shfl_xor_sync(0xffffffffu, s2, o);
    }
    if (lane == 0) { sh1[w] = s1; sh2[w] = s2; }
    __syncthreads();
    float t1 = 0.f, t2 = 0.f;
    #pragma unroll
    for (int i = 0; i < 8; i++) { t1 += sh1[i]; t2 += sh2[i]; }
    const float i1 = 1.f / fmaxf(sqrtf(t1), 1e-12f);
    const float i2 = 1.f / fmaxf(sqrtf(t2), 1e-12f);
    if (t == 0) { g_inv1[row] = i1; g_inv2[row] = i2; }

    #pragma unroll
    for (int p = 0; p < 4; p++) {
        const size_t off = base + (size_t)(p * 256 + t) * 4;
        const float a[4]  = {va[p].x, va[p].y, va[p].z, va[p].w};
        const float bb[4] = {vb[p].x, vb[p].y, vb[p].z, vb[p].w};
        bf16 sv[4], r1v[4], r2v[4];
        float4 x12;
        #pragma unroll
        for (int i = 0; i < 4; i++) {
            sv[i]  = __float2bfloat16(i1 * a[i] + i2 * bb[i]);
            r1v[i] = __float2bfloat16(a[i]);
            r2v[i] = __float2bfloat16(bb[i]);
        }
        x12.x = a[0] + bb[0]; x12.y = a[1] + bb[1];
        x12.z = a[2] + bb[2]; x12.w = a[3] + bb[3];
        *(uint2*)(g_s  + off) = *(const uint2*)sv;
        *(uint2*)(g_r1 + off) = *(const uint2*)r1v;
        *(uint2*)(g_r2 + off) = *(const uint2*)r2v;
        *(float4*)(g_x12 + off) = x12;
    }
}

// ---------------------------------------------------------------------------
// Kernel 2: gram HMMA, split-K=2, single-sync 4-stage pipeline.
// grid (2 dblk, 2 cblk, B*4): z = b*4 + mat*2 + ks.
// ---------------------------------------------------------------------------
__global__ __launch_bounds__(256, 2) void gram_mma() {
    extern __shared__ char sm[];
    const uint32_t smb = smem_u32(sm);
    const int t = threadIdx.x, w = t >> 5, l = t & 31;
    const int dblk = blockIdx.x, cblk = blockIdx.y;
    const int zi = blockIdx.z;
    const int b = zi >> 2, mat = (zi >> 1) & 1, ks = zi & 1;

    const bf16* Ag = g_s + (size_t)b * CN + (size_t)(cblk * 128) * NPIX + ks * 2048;
    const bf16* Bg = (mat ? g_r2 : g_r1) + (size_t)b * CN
                   + (size_t)(dblk * 128) * NPIX + ks * 2048;

    const int mw0 = (w >> 2) * 64, nw0 = (w & 3) * 32;
    const int fr  = t >> 2;
    const int fkB = (t & 3) * 16;
    const int fkE = (t & 3) * 8;
    const int lA_row = l & 15, lA_k = (l >> 4) * 8;
    const int q = l >> 3;
    const int lB_row = ((q >> 1) * 8) + (l & 7);
    const int lB_k = (q & 1) * 8;

    float acc[4][4][4] = {};
    const int niter = 2048 / 32;     // 64

    #pragma unroll
    for (int s = 0; s < PIPE - 1; s++) {
        fill_gram(Ag, NPIX, Bg, NPIX, s * 32, smb + s * STAGE_B, fr, fkB, fkE);
        CP_COMMIT();
    }
    #pragma unroll 1
    for (int it = 0; it < niter; it++) {
        CP_WAIT(PIPE - 2);
        __syncthreads();
        if (it + PIPE - 1 < niter)
            fill_gram(Ag, NPIX, Bg, NPIX, (it + PIPE - 1) * 32,
                      smb + ((it + PIPE - 1) & (PIPE - 1)) * STAGE_B, fr, fkB, fkE);
        CP_COMMIT();
        const uint32_t Abase = smb + (it & (PIPE - 1)) * STAGE_B;
        compute_stage(Abase, Abase + TILE_B, mw0, nw0, lA_row, lA_k, lB_row, lB_k, acc);
    }

    float* S = g_Sp[mat * 2 + ks] + (size_t)(b * CH + cblk * 128) * CH + dblk * 128;
    const int rr = l >> 2, cc = (l & 3) * 2;
    #pragma unroll
    for (int i = 0; i < 4; i++)
        #pragma unroll
        for (int j = 0; j < 4; j++) {
            const int c_ = mw0 + i * 16 + rr;
            const int d_ = nw0 + j * 8 + cc;
            float2 lo = {acc[i][j][0], acc[i][j][1]};
            float2 hi = {acc[i][j][2], acc[i][j][3]};
            *(float2*)&S[(size_t)c_ * CH + d_] = lo;
            *(float2*)&S[(size_t)(c_ + 8) * CH + d_] = hi;
        }
}

// ---------------------------------------------------------------------------
// Kernel 3: warp-per-row softmax. 8 rows per 256-thread CTA, no __syncthreads.
// grid = B*CH/8 = 512 blocks.
// ---------------------------------------------------------------------------
__global__ __launch_bounds__(256) void softmax_kernel() {
    const int wid = threadIdx.x >> 5, lane = threadIdx.x & 31;
    const int row = blockIdx.x * 8 + wid;          // b*CH + c
    const size_t base = (size_t)row * CH + lane * 8;
    const int invb = (row >> 8) << 8;              // b*CH
    const int d0 = lane * 8;

    float v1[8], v2[8];
    {
        const float4 p0a = *(const float4*)&g_Sp[0][base];
        const float4 p0b = *(const float4*)&g_Sp[0][base + 4];
        const float4 p1a = *(const float4*)&g_Sp[1][base];
        const float4 p1b = *(const float4*)&g_Sp[1][base + 4];
        const float4 p2a = *(const float4*)&g_Sp[2][base];
        const float4 p2b = *(const float4*)&g_Sp[2][base + 4];
        const float4 p3a = *(const float4*)&g_Sp[3][base];
        const float4 p3b = *(const float4*)&g_Sp[3][base + 4];
        const float4 i1a = *(const float4*)&g_inv1[invb + d0];
        const float4 i1b = *(const float4*)&g_inv1[invb + d0 + 4];
        const float4 i2a = *(const float4*)&g_inv2[invb + d0];
        const float4 i2b = *(const float4*)&g_inv2[invb + d0 + 4];
        const float* q0a = (const float*)&p0a; const float* q0b = (const float*)&p0b;
        const float* q1a = (const float*)&p1a; const float* q1b = (const float*)&p1b;
        const float* q2a = (const float*)&p2a; const float* q2b = (const float*)&p2b;
        const float* q3a = (const float*)&p3a; const float* q3b = (const float*)&p3b;
        const float* j1a = (const float*)&i1a; const float* j1b = (const float*)&i1b;
        const float* j2a = (const float*)&i2a; const float* j2b = (const float*)&i2b;
        #pragma unroll
        for (int i = 0; i < 4; i++) {
            v1[i]     = (q0a[i] + q1a[i]) * j1a[i];
            v1[i + 4] = (q0b[i] + q1b[i]) * j1b[i];
            v2[i]     = (q2a[i] + q3a[i]) * j2a[i];
            v2[i + 4] = (q2b[i] + q3b[i]) * j2b[i];
        }
    }

    float m1 = v1[0], m2 = v2[0];
    #pragma unroll
    for (int i = 1; i < 8; i++) { m1 = fmaxf(m1, v1[i]); m2 = fmaxf(m2, v2[i]); }
    #pragma unroll
    for (int o = 16; o; o >>= 1) {
        m1 = fmaxf(m1, __shfl_xor_sync(0xffffffffu, m1, o));
        m2 = fmaxf(m2, __shfl_xor_sync(0xffffffffu, m2, o));
    }
    float s1 = 0.f, s2 = 0.f;
    #pragma unroll
    for (int i = 0; i < 8; i++) {
        v1[i] = __expf(v1[i] - m1); s1 += v1[i];
        v2[i] = __expf(v2[i] - m2); s2 += v2[i];
    }
    #pragma unroll
    for (int o = 16; o; o >>= 1) {
        s1 += __shfl_xor_sync(0xffffffffu, s1, o);
        s2 += __shfl_xor_sync(0xffffffffu, s2, o);
    }
    const float r1 = 1.f / s1, r2 = 1.f / s2;
    uint32_t o1[4], o2[4];
    #pragma unroll
    for (int i = 0; i < 4; i++) {
        __nv_bfloat162 h1 = __floats2bfloat162_rn(v1[2 * i] * r1, v1[2 * i + 1] * r1);
        __nv_bfloat162 h2 = __floats2bfloat162_rn(v2[2 * i] * r2, v2[2 * i + 1] * r2);
        o1[i] = *(const uint32_t*)&h1;
        o2[i] = *(const uint32_t*)&h2;
    }
    *(uint4*)(g_A1 + base) = *(const uint4*)o1;
    *(uint4*)(g_A2 + base) = *(const uint4*)o2;
}

// ---------------------------------------------------------------------------
// Kernel 4: back-projection HMMA (trans-B), fused 16-iter single-sync loop.
// Residual read from precomputed fp32 g_x12. grid (2 cblk, 32 nblk, B).
// ---------------------------------------------------------------------------
#define ZPITCH 132

__global__ __launch_bounds__(256, 2) void out_mma(float* __restrict__ out) {
    extern __shared__ char sm[];
    const uint32_t smb = smem_u32(sm);
    const int t = threadIdx.x, w = t >> 5, l = t & 31;
    const int cblk = blockIdx.x, nblk = blockIdx.y, b = blockIdx.z;
    const int n0 = nblk * 128, c0 = cblk * 128;

    const bf16* Apt[2] = { g_A1 + (size_t)(b * CH + c0) * CH,
                           g_A2 + (size_t)(b * CH + c0) * CH };
    const bf16* Bpt[2] = { g_r1 + (size_t)b * CN + n0,
                           g_r2 + (size_t)b * CN + n0 };

    const int mw0 = (w >> 2) * 64, nw0 = (w & 3) * 32;
    const int fr  = t >> 2;
    const int fkB = (t & 3) * 16;
    const int fkE = (t & 3) * 8;
    const int lA_row = l & 15, lA_k = (l >> 4) * 8;
    const int q = l >> 3;
    const int br0 = t >> 4, bc0 = t & 15;

    float acc[4][4][4] = {};
    const int niter = 16;            // 2 mats x 8 k-chunks

    #pragma unroll
    for (int s = 0; s < PIPE - 1; s++) {
        fill_tb(Apt[s >> 3], CH, Bpt[s >> 3], NPIX, (s & 7) * 32,
                smb + s * OSTAGE_B, fr, fkB, fkE, br0, bc0);
        CP_COMMIT();
    }
    #pragma unroll 1
    for (int it = 0; it < niter; it++) {
        CP_WAIT(PIPE - 2);
        __syncthreads();
        if (it + PIPE - 1 < niter) {
            const int nx = it + PIPE - 1;
            fill_tb(Apt[nx >> 3], CH, Bpt[nx >> 3], NPIX, (nx & 7) * 32,
                    smb + (nx & (PIPE - 1)) * OSTAGE_B, fr, fkB, fkE, br0, bc0);
        }
        CP_COMMIT();
        const uint32_t Abase = smb + (it & (PIPE - 1)) * OSTAGE_B;
        compute_stage_tb(Abase, Abase + TILE_B, mw0, nw0, lA_row, lA_k, q, l, acc);
    }
    __syncthreads();

    const int rr = l >> 2, cc = (l & 3) * 2;
    float* Zs = (float*)sm;          // [64 n][ZPITCH c]

    #pragma unroll 1
    for (int h = 0; h < 2; h++) {
        if ((nw0 >> 6) == h) {
            const int nb = nw0 - h * 64;
            #pragma unroll
            for (int i = 0; i < 4; i++)
                #pragma unroll
                for (int j = 0; j < 4; j++) {
                    const int cl = mw0 + i * 16 + rr;
                    const int nl = nb + j * 8 + cc;
                    Zs[(size_t)nl * ZPITCH + cl]           = acc[i][j][0];
                    Zs[(size_t)(nl + 1) * ZPITCH + cl]     = acc[i][j][1];
                    Zs[(size_t)nl * ZPITCH + cl + 8]       = acc[i][j][2];
                    Zs[(size_t)(nl + 1) * ZPITCH + cl + 8] = acc[i][j][3];
                }
        }
        __syncthreads();
        #pragma unroll
        for (int p = 0; p < 8; p++) {
            const int idx = t + p * 256;
            const int n = idx >> 5, c4 = (idx & 31) * 4;
            const float4 z = *(const float4*)&Zs[(size_t)n * ZPITCH + c4];
            const size_t g = (size_t)b * CN + (size_t)(n0 + h * 64 + n) * CH + c0 + c4;
            const float4 s12 = *(const float4*)(g_x12 + g);
            float4 o;
            o.x = z.x + s12.x; o.y = z.y + s12.y;
            o.z = z.z + s12.z; o.w = z.w + s12.w;
            *(float4*)(out + g) = o;
        }
        __syncthreads();
    }
}

// ---------------------------------------------------------------------------
extern "C" void kernel_launch(void* const* d_in, const int* in_sizes, int n_in,
                              void* d_out, int out_size) {
    (void)in_sizes; (void)n_in; (void)out_size;
    const float* x1 = (const float*)d_in[0];
    const float* x2 = (const float*)d_in[1];
    float* out = (float*)d_out;

    cudaFuncSetAttribute(gram_mma, cudaFuncAttributeMaxDynamicSharedMemorySize, SM_MAIN);
    cudaFuncSetAttribute(out_mma,  cudaFuncAttributeMaxDynamicSharedMemorySize, SM_OUT);

    normconv_kernel<<<BATCH * CH, 256>>>(x1, x2);
    gram_mma<<<dim3(2, 2, BATCH * 4), 256, SM_MAIN>>>();
    softmax_kernel<<<BATCH * CH / 8, 256>>>();
    out_mma<<<dim3(2, 32, BATCH), 256, SM_OUT>>>(out);
}

// round 13
// speedup vs baseline: 1.0443x; 1.0135x over previous
#include <cuda_runtime.h>
#include <cuda_bf16.h>
#include <math.h>
#include <stdint.h>

#define BATCH 16
#define CH    256
#define NPIX  4096
#define CN    (CH * NPIX)

typedef __nv_bfloat16 bf16;

// ---------------- device-global scratch (allocation-free) ----------------
__device__ float g_inv1[BATCH * CH];
__device__ float g_inv2[BATCH * CH];
__device__ __align__(16) bf16 g_s [BATCH * CN];   // inv1*x1+inv2*x2 [b][c][n]
__device__ __align__(16) bf16 g_r1[BATCH * CN];   // raw bf16 x1     [b][c][n]
__device__ __align__(16) bf16 g_r2[BATCH * CN];   // raw bf16 x2     [b][c][n]
__device__ __align__(16) float g_Sp[4][BATCH * CH * CH]; // partials [mat*2+ks]
__device__ __align__(16) bf16 g_A1[BATCH * CH * CH];     // bf16 probs
__device__ __align__(16) bf16 g_A2[BATCH * CH * CH];

// ---------------- PTX helpers ----------------
__device__ __forceinline__ uint32_t smem_u32(const void* p) {
    uint32_t a;
    asm("{ .reg .u64 t; cvta.to.shared.u64 t, %1; cvt.u32.u64 %0, t; }" : "=r"(a) : "l"(p));
    return a;
}
__device__ __forceinline__ void cpasync16(uint32_t s, const void* g) {
    asm volatile("cp.async.cg.shared.global [%0], [%1], 16;" :: "r"(s), "l"(g));
}
#define CP_COMMIT() asm volatile("cp.async.commit_group;")
#define CP_WAIT(N)  asm volatile("cp.async.wait_group %0;" :: "n"(N))

__device__ __forceinline__ void ldm_x4(uint32_t* r, uint32_t a) {
    asm volatile("ldmatrix.sync.aligned.m8n8.x4.shared.b16 {%0,%1,%2,%3}, [%4];"
        : "=r"(r[0]), "=r"(r[1]), "=r"(r[2]), "=r"(r[3]) : "r"(a));
}
__device__ __forceinline__ void ldm_x4t(uint32_t* r, uint32_t a) {
    asm volatile("ldmatrix.sync.aligned.m8n8.x4.trans.shared.b16 {%0,%1,%2,%3}, [%4];"
        : "=r"(r[0]), "=r"(r[1]), "=r"(r[2]), "=r"(r[3]) : "r"(a));
}
__device__ __forceinline__ void mma16816(float* c, const uint32_t* a, const uint32_t* b) {
    asm volatile("mma.sync.aligned.m16n8k16.row.col.f32.bf16.bf16.f32 "
        "{%0,%1,%2,%3}, {%4,%5,%6,%7}, {%8,%9}, {%0,%1,%2,%3};"
        : "+f"(c[0]), "+f"(c[1]), "+f"(c[2]), "+f"(c[3])
        : "r"(a[0]), "r"(a[1]), "r"(a[2]), "r"(a[3]), "r"(b[0]), "r"(b[1]));
}

// BK = 64. Row-major operand tiles: 64 bf16 = 128 B data + 16 pad = 144 B pitch
// (144/16 = 9, odd -> ldmatrix 8-row gathers conflict-free).
#define AROW_B  144
#define ATILE_B (128 * AROW_B)          // 18432 B
#define PIPE    2
// gram: A tile + B tile (both 128 rows x 64 k)
#define GSTAGE_B (2 * ATILE_B)          // 36864 B
#define SM_GRAM  (PIPE * GSTAGE_B)      // 73728 B
// out: B tile [64 k][128 n] bf16, pitch 272 B (17x16B, conflict-free)
#define BROW_B   272
#define OBTILE_B (64 * BROW_B)          // 17408 B
#define OSTAGE_B (ATILE_B + OBTILE_B)   // 35840 B
#define SM_OUT   (PIPE * OSTAGE_B)      // 71680 B

// ---------------------------------------------------------------------------
// Stage fills (256 threads, BK=64)
// ---------------------------------------------------------------------------
__device__ __forceinline__ void fill_gram(const bf16* __restrict__ Ag, int lda,
                                          const bf16* __restrict__ Bg, int ldb,
                                          int k0, uint32_t st, int t) {
    const int r  = t >> 1;               // 0..127
    const int c0 = (t & 1) * 4;          // chunk base (16B units)
    #pragma unroll
    for (int i = 0; i < 4; i++) {
        const int c = c0 + i;
        cpasync16(st + r * AROW_B + c * 16, Ag + (size_t)r * lda + k0 + c * 8);
        cpasync16(st + ATILE_B + r * AROW_B + c * 16,
                  Bg + (size_t)r * ldb + k0 + c * 8);
    }
}

__device__ __forceinline__ void fill_tb(const bf16* __restrict__ Ag, int lda,
                                        const bf16* __restrict__ Bg, int ldb,
                                        int k0, uint32_t st, int t) {
    const int r  = t >> 1;
    const int c0 = (t & 1) * 4;
    #pragma unroll
    for (int i = 0; i < 4; i++) {
        const int c = c0 + i;
        cpasync16(st + r * AROW_B + c * 16, Ag + (size_t)r * lda + k0 + c * 8);
    }
    const uint32_t sb = st + ATILE_B;
    const int br = t >> 4;               // 0..15
    const int bc = t & 15;               // 16B chunk along n
    #pragma unroll
    for (int j = 0; j < 4; j++) {
        cpasync16(sb + (br + j * 16) * BROW_B + bc * 16,
                  Bg + (size_t)(k0 + br + j * 16) * ldb + bc * 8);
    }
}

// ---------------------------------------------------------------------------
// Compute one 64-k stage (4 ks sub-steps of k=16).
// ---------------------------------------------------------------------------
__device__ __forceinline__ void compute_stage(uint32_t Abase, uint32_t Bbase,
                                              int mw0, int nw0, int lA_row, int lA_k,
                                              int lB_row, int lB_k,
                                              float acc[4][4][4]) {
    #pragma unroll
    for (int ks = 0; ks < 4; ks++) {
        uint32_t afr[4][4], bfr[4][2];
        #pragma unroll
        for (int i = 0; i < 4; i++)
            ldm_x4(afr[i], Abase + (mw0 + i * 16 + lA_row) * AROW_B
                                 + (ks * 16 + lA_k) * 2);
        #pragma unroll
        for (int p = 0; p < 2; p++) {
            uint32_t r[4];
            ldm_x4(r, Bbase + (nw0 + p * 16 + lB_row) * AROW_B
                            + (ks * 16 + lB_k) * 2);
            bfr[p * 2][0] = r[0]; bfr[p * 2][1] = r[1];
            bfr[p * 2 + 1][0] = r[2]; bfr[p * 2 + 1][1] = r[3];
        }
        #pragma unroll
        for (int i = 0; i < 4; i++)
            #pragma unroll
            for (int j = 0; j < 4; j++)
                mma16816(acc[i][j], afr[i], bfr[j]);
    }
}

__device__ __forceinline__ void compute_stage_tb(uint32_t Abase, uint32_t Bbase,
                                                 int mw0, int nw0, int lA_row, int lA_k,
                                                 int q, int l,
                                                 float acc[4][4][4]) {
    #pragma unroll
    for (int ks = 0; ks < 4; ks++) {
        uint32_t afr[4][4], bfr[4][2];
        #pragma unroll
        for (int i = 0; i < 4; i++)
            ldm_x4(afr[i], Abase + (mw0 + i * 16 + lA_row) * AROW_B
                                 + (ks * 16 + lA_k) * 2);
        #pragma unroll
        for (int p = 0; p < 2; p++) {
            uint32_t r[4];
            ldm_x4t(r, Bbase + (ks * 16 + (q & 1) * 8 + (l & 7)) * BROW_B
                             + (nw0 + p * 16 + (q >> 1) * 8) * 2);
            bfr[p * 2][0] = r[0]; bfr[p * 2][1] = r[1];
            bfr[p * 2 + 1][0] = r[2]; bfr[p * 2 + 1][1] = r[3];
        }
        #pragma unroll
        for (int i = 0; i < 4; i++)
            #pragma unroll
            for (int j = 0; j < 4; j++)
                mma16816(acc[i][j], afr[i], bfr[j]);
    }
}

// ---------------------------------------------------------------------------
// Kernel 1: fused norms + bf16 conversion.
// ---------------------------------------------------------------------------
__global__ __launch_bounds__(256) void normconv_kernel(const float* __restrict__ x1,
                                                       const float* __restrict__ x2) {
    const int row = blockIdx.x;                     // b*CH + c
    const int t = threadIdx.x;
    const size_t base = (size_t)row * NPIX;
    float4 va[4], vb[4];
    float s1 = 0.f, s2 = 0.f;
    #pragma unroll
    for (int p = 0; p < 4; p++) {
        va[p] = *(const float4*)(x1 + base + (size_t)(p * 256 + t) * 4);
        vb[p] = *(const float4*)(x2 + base + (size_t)(p * 256 + t) * 4);
        s1 += va[p].x * va[p].x + va[p].y * va[p].y + va[p].z * va[p].z + va[p].w * va[p].w;
        s2 += vb[p].x * vb[p].x + vb[p].y * vb[p].y + vb[p].z * vb[p].z + vb[p].w * vb[p].w;
    }
    __shared__ float sh1[8], sh2[8];
    const int lane = t & 31, w = t >> 5;
    #pragma unroll
    for (int o = 16; o; o >>= 1) {
        s1 += __shfl_xor_sync(0xffffffffu, s1, o);
        s2 += __shfl_xor_sync(0xffffffffu, s2, o);
    }
    if (lane == 0) { sh1[w] = s1; sh2[w] = s2; }
    __syncthreads();
    float t1 = 0.f, t2 = 0.f;
    #pragma unroll
    for (int i = 0; i < 8; i++) { t1 += sh1[i]; t2 += sh2[i]; }
    const float i1 = 1.f / fmaxf(sqrtf(t1), 1e-12f);
    const float i2 = 1.f / fmaxf(sqrtf(t2), 1e-12f);
    if (t == 0) { g_inv1[row] = i1; g_inv2[row] = i2; }

    #pragma unroll
    for (int p = 0; p < 4; p++) {
        const size_t off = base + (size_t)(p * 256 + t) * 4;
        const float a[4]  = {va[p].x, va[p].y, va[p].z, va[p].w};
        const float bb[4] = {vb[p].x, vb[p].y, vb[p].z, vb[p].w};
        bf16 sv[4], r1v[4], r2v[4];
        #pragma unroll
        for (int i = 0; i < 4; i++) {
            sv[i]  = __float2bfloat16(i1 * a[i] + i2 * bb[i]);
            r1v[i] = __float2bfloat16(a[i]);
            r2v[i] = __float2bfloat16(bb[i]);
        }
        *(uint2*)(g_s  + off) = *(const uint2*)sv;
        *(uint2*)(g_r1 + off) = *(const uint2*)r1v;
        *(uint2*)(g_r2 + off) = *(const uint2*)r2v;
    }
}

// ---------------------------------------------------------------------------
// Kernel 2: gram HMMA, split-K=2, BK=64, PIPE=2 single-sync.
// grid (2 dblk, 2 cblk, B*4): z = b*4 + mat*2 + ks.
// ---------------------------------------------------------------------------
__global__ __launch_bounds__(256, 2) void gram_mma() {
    extern __shared__ char sm[];
    const uint32_t smb = smem_u32(sm);
    const int t = threadIdx.x, w = t >> 5, l = t & 31;
    const int dblk = blockIdx.x, cblk = blockIdx.y;
    const int zi = blockIdx.z;
    const int b = zi >> 2, mat = (zi >> 1) & 1, ks = zi & 1;

    const bf16* Ag = g_s + (size_t)b * CN + (size_t)(cblk * 128) * NPIX + ks * 2048;
    const bf16* Bg = (mat ? g_r2 : g_r1) + (size_t)b * CN
                   + (size_t)(dblk * 128) * NPIX + ks * 2048;

    const int mw0 = (w >> 2) * 64, nw0 = (w & 3) * 32;
    const int lA_row = l & 15, lA_k = (l >> 4) * 8;
    const int q = l >> 3;
    const int lB_row = ((q >> 1) * 8) + (l & 7);
    const int lB_k = (q & 1) * 8;

    float acc[4][4][4] = {};
    const int niter = 2048 / 64;     // 32

    fill_gram(Ag, NPIX, Bg, NPIX, 0, smb, t);
    CP_COMMIT();
    #pragma unroll 1
    for (int it = 0; it < niter; it++) {
        CP_WAIT(0);
        __syncthreads();
        if (it + 1 < niter)
            fill_gram(Ag, NPIX, Bg, NPIX, (it + 1) * 64,
                      smb + ((it + 1) & 1) * GSTAGE_B, t);
        CP_COMMIT();
        const uint32_t Abase = smb + (it & 1) * GSTAGE_B;
        compute_stage(Abase, Abase + ATILE_B, mw0, nw0, lA_row, lA_k, lB_row, lB_k, acc);
    }

    float* S = g_Sp[mat * 2 + ks] + (size_t)(b * CH + cblk * 128) * CH + dblk * 128;
    const int rr = l >> 2, cc = (l & 3) * 2;
    #pragma unroll
    for (int i = 0; i < 4; i++)
        #pragma unroll
        for (int j = 0; j < 4; j++) {
            const int c_ = mw0 + i * 16 + rr;
            const int d_ = nw0 + j * 8 + cc;
            float2 lo = {acc[i][j][0], acc[i][j][1]};
            float2 hi = {acc[i][j][2], acc[i][j][3]};
            *(float2*)&S[(size_t)c_ * CH + d_] = lo;
            *(float2*)&S[(size_t)(c_ + 8) * CH + d_] = hi;
        }
}

// ---------------------------------------------------------------------------
// Kernel 3: warp-per-row softmax. 8 rows per 256-thread CTA, no __syncthreads.
// ---------------------------------------------------------------------------
__global__ __launch_bounds__(256) void softmax_kernel() {
    const int wid = threadIdx.x >> 5, lane = threadIdx.x & 31;
    const int row = blockIdx.x * 8 + wid;          // b*CH + c
    const size_t base = (size_t)row * CH + lane * 8;
    const int invb = (row >> 8) << 8;              // b*CH
    const int d0 = lane * 8;

    float v1[8], v2[8];
    {
        const float4 p0a = *(const float4*)&g_Sp[0][base];
        const float4 p0b = *(const float4*)&g_Sp[0][base + 4];
        const float4 p1a = *(const float4*)&g_Sp[1][base];
        const float4 p1b = *(const float4*)&g_Sp[1][base + 4];
        const float4 p2a = *(const float4*)&g_Sp[2][base];
        const float4 p2b = *(const float4*)&g_Sp[2][base + 4];
        const float4 p3a = *(const float4*)&g_Sp[3][base];
        const float4 p3b = *(const float4*)&g_Sp[3][base + 4];
        const float4 i1a = *(const float4*)&g_inv1[invb + d0];
        const float4 i1b = *(const float4*)&g_inv1[invb + d0 + 4];
        const float4 i2a = *(const float4*)&g_inv2[invb + d0];
        const float4 i2b = *(const float4*)&g_inv2[invb + d0 + 4];
        const float* q0a = (const float*)&p0a; const float* q0b = (const float*)&p0b;
        const float* q1a = (const float*)&p1a; const float* q1b = (const float*)&p1b;
        const float* q2a = (const float*)&p2a; const float* q2b = (const float*)&p2b;
        const float* q3a = (const float*)&p3a; const float* q3b = (const float*)&p3b;
        const float* j1a = (const float*)&i1a; const float* j1b = (const float*)&i1b;
        const float* j2a = (const float*)&i2a; const float* j2b = (const float*)&i2b;
        #pragma unroll
        for (int i = 0; i < 4; i++) {
            v1[i]     = (q0a[i] + q1a[i]) * j1a[i];
            v1[i + 4] = (q0b[i] + q1b[i]) * j1b[i];
            v2[i]     = (q2a[i] + q3a[i]) * j2a[i];
            v2[i + 4] = (q2b[i] + q3b[i]) * j2b[i];
        }
    }

    float m1 = v1[0], m2 = v2[0];
    #pragma unroll
    for (int i = 1; i < 8; i++) { m1 = fmaxf(m1, v1[i]); m2 = fmaxf(m2, v2[i]); }
    #pragma unroll
    for (int o = 16; o; o >>= 1) {
        m1 = fmaxf(m1, __shfl_xor_sync(0xffffffffu, m1, o));
        m2 = fmaxf(m2, __shfl_xor_sync(0xffffffffu, m2, o));
    }
    float s1 = 0.f, s2 = 0.f;
    #pragma unroll
    for (int i = 0; i < 8; i++) {
        v1[i] = __expf(v1[i] - m1); s1 += v1[i];
        v2[i] = __expf(v2[i] - m2); s2 += v2[i];
    }
    #pragma unroll
    for (int o = 16; o; o >>= 1) {
        s1 += __shfl_xor_sync(0xffffffffu, s1, o);
        s2 += __shfl_xor_sync(0xffffffffu, s2, o);
    }
    const float r1 = 1.f / s1, r2 = 1.f / s2;
    uint32_t o1[4], o2[4];
    #pragma unroll
    for (int i = 0; i < 4; i++) {
        __nv_bfloat162 h1 = __floats2bfloat162_rn(v1[2 * i] * r1, v1[2 * i + 1] * r1);
        __nv_bfloat162 h2 = __floats2bfloat162_rn(v2[2 * i] * r2, v2[2 * i + 1] * r2);
        o1[i] = *(const uint32_t*)&h1;
        o2[i] = *(const uint32_t*)&h2;
    }
    *(uint4*)(g_A1 + base) = *(const uint4*)o1;
    *(uint4*)(g_A2 + base) = *(const uint4*)o2;
}

// ---------------------------------------------------------------------------
// Kernel 4: back-projection HMMA (trans-B), BK=64, PIPE=2 single-sync,
// fused 8-iter loop (2 mats x 4 chunks). grid (2 cblk, 32 nblk, B).
// ---------------------------------------------------------------------------
#define ZPITCH 132

__global__ __launch_bounds__(256, 2) void out_mma(const float* __restrict__ x1,
                                                  const float* __restrict__ x2,
                                                  float* __restrict__ out) {
    extern __shared__ char sm[];
    const uint32_t smb = smem_u32(sm);
    const int t = threadIdx.x, w = t >> 5, l = t & 31;
    const int cblk = blockIdx.x, nblk = blockIdx.y, b = blockIdx.z;
    const int n0 = nblk * 128, c0 = cblk * 128;

    const bf16* Apt[2] = { g_A1 + (size_t)(b * CH + c0) * CH,
                           g_A2 + (size_t)(b * CH + c0) * CH };
    const bf16* Bpt[2] = { g_r1 + (size_t)b * CN + n0,
                           g_r2 + (size_t)b * CN + n0 };

    const int mw0 = (w >> 2) * 64, nw0 = (w & 3) * 32;
    const int lA_row = l & 15, lA_k = (l >> 4) * 8;
    const int q = l >> 3;

    float acc[4][4][4] = {};
    const int niter = 8;             // 2 mats x 4 k-chunks of 64

    fill_tb(Apt[0], CH, Bpt[0], NPIX, 0, smb, t);
    CP_COMMIT();
    #pragma unroll 1
    for (int it = 0; it < niter; it++) {
        CP_WAIT(0);
        __syncthreads();
        if (it + 1 < niter) {
            const int nx = it + 1;
            fill_tb(Apt[nx >> 2], CH, Bpt[nx >> 2], NPIX, (nx & 3) * 64,
                    smb + (nx & 1) * OSTAGE_B, t);
        }
        CP_COMMIT();
        const uint32_t Abase = smb + (it & 1) * OSTAGE_B;
        compute_stage_tb(Abase, Abase + ATILE_B, mw0, nw0, lA_row, lA_k, q, l, acc);
    }
    __syncthreads();

    const int rr = l >> 2, cc = (l & 3) * 2;
    float* Zs = (float*)sm;          // [64 n][ZPITCH c]

    #pragma unroll 1
    for (int h = 0; h < 2; h++) {
        if ((nw0 >> 6) == h) {
            const int nb = nw0 - h * 64;
            #pragma unroll
            for (int i = 0; i < 4; i++)
                #pragma unroll
                for (int j = 0; j < 4; j++) {
                    const int cl = mw0 + i * 16 + rr;
                    const int nl = nb + j * 8 + cc;
                    Zs[(size_t)nl * ZPITCH + cl]           = acc[i][j][0];
                    Zs[(size_t)(nl + 1) * ZPITCH + cl]     = acc[i][j][1];
                    Zs[(size_t)nl * ZPITCH + cl + 8]       = acc[i][j][2];
                    Zs[(size_t)(nl + 1) * ZPITCH + cl + 8] = acc[i][j][3];
                }
        }
        __syncthreads();
        #pragma unroll
        for (int p = 0; p < 8; p++) {
            const int idx = t + p * 256;
            const int n = idx >> 5, c4 = (idx & 31) * 4;
            const float4 z = *(const float4*)&Zs[(size_t)n * ZPITCH + c4];
            const size_t g = (size_t)b * CN + (size_t)(n0 + h * 64 + n) * CH + c0 + c4;
            const float4 a = *(const float4*)(x1 + g);
            const float4 bb = *(const float4*)(x2 + g);
            float4 o;
            o.x = z.x + a.x + bb.x; o.y = z.y + a.y + bb.y;
            o.z = z.z + a.z + bb.z; o.w = z.w + a.w + bb.w;
            *(float4*)(out + g) = o;
        }
        __syncthreads();
    }
}

// ---------------------------------------------------------------------------
extern "C" void kernel_launch(void* const* d_in, const int* in_sizes, int n_in,
                              void* d_out, int out_size) {
    (void)in_sizes; (void)n_in; (void)out_size;
    const float* x1 = (const float*)d_in[0];
    const float* x2 = (const float*)d_in[1];
    float* out = (float*)d_out;

    cudaFuncSetAttribute(gram_mma, cudaFuncAttributeMaxDynamicSharedMemorySize, SM_GRAM);
    cudaFuncSetAttribute(out_mma,  cudaFuncAttributeMaxDynamicSharedMemorySize, SM_OUT);

    normconv_kernel<<<BATCH * CH, 256>>>(x1, x2);
    gram_mma<<<dim3(2, 2, BATCH * 4), 256, SM_GRAM>>>();
    softmax_kernel<<<BATCH * CH / 8, 256>>>();
    out_mma<<<dim3(2, 32, BATCH), 256, SM_OUT>>>(x1, x2, out);
}

// round 15
// speedup vs baseline: 1.1973x; 1.1465x over previous
#include <cuda_runtime.h>
#include <cuda_bf16.h>
#include <math.h>
#include <stdint.h>

#define BATCH 16
#define CH    256
#define NPIX  4096
#define CN    (CH * NPIX)

typedef __nv_bfloat16 bf16;

// ---------------- device-global scratch (allocation-free) ----------------
__device__ float g_inv1[BATCH * CH];
__device__ float g_inv2[BATCH * CH];
__device__ __align__(16) bf16 g_s [BATCH * CN];   // inv1*x1+inv2*x2 [b][c][n]
__device__ __align__(16) bf16 g_r1[BATCH * CN];   // raw bf16 x1     [b][c][n]
__device__ __align__(16) bf16 g_r2[BATCH * CN];   // raw bf16 x2     [b][c][n]
__device__ __align__(16) float g_Sp[4][BATCH * CH * CH]; // partials [mat*2+ks]
__device__ __align__(16) bf16 g_A1[BATCH * CH * CH];     // bf16 probs
__device__ __align__(16) bf16 g_A2[BATCH * CH * CH];

// ---------------- PTX helpers ----------------
__device__ __forceinline__ uint32_t smem_u32(const void* p) {
    uint32_t a;
    asm("{ .reg .u64 t; cvta.to.shared.u64 t, %1; cvt.u32.u64 %0, t; }" : "=r"(a) : "l"(p));
    return a;
}
__device__ __forceinline__ void cpasync16(uint32_t s, const void* g) {
    asm volatile("cp.async.cg.shared.global [%0], [%1], 16;" :: "r"(s), "l"(g));
}
#define CP_COMMIT() asm volatile("cp.async.commit_group;")
#define CP_WAIT(N)  asm volatile("cp.async.wait_group %0;" :: "n"(N))

__device__ __forceinline__ void ldm_x4(uint32_t* r, uint32_t a) {
    asm volatile("ldmatrix.sync.aligned.m8n8.x4.shared.b16 {%0,%1,%2,%3}, [%4];"
        : "=r"(r[0]), "=r"(r[1]), "=r"(r[2]), "=r"(r[3]) : "r"(a));
}
__device__ __forceinline__ void ldm_x4t(uint32_t* r, uint32_t a) {
    asm volatile("ldmatrix.sync.aligned.m8n8.x4.trans.shared.b16 {%0,%1,%2,%3}, [%4];"
        : "=r"(r[0]), "=r"(r[1]), "=r"(r[2]), "=r"(r[3]) : "r"(a));
}
__device__ __forceinline__ void mma16816(float* c, const uint32_t* a, const uint32_t* b) {
    asm volatile("mma.sync.aligned.m16n8k16.row.col.f32.bf16.bf16.f32 "
        "{%0,%1,%2,%3}, {%4,%5,%6,%7}, {%8,%9}, {%0,%1,%2,%3};"
        : "+f"(c[0]), "+f"(c[1]), "+f"(c[2]), "+f"(c[3])
        : "r"(a[0]), "r"(a[1]), "r"(a[2]), "r"(a[3]), "r"(b[0]), "r"(b[1]));
}

// A/B tiles 128 rows x 32 bf16, padded row = 80 B.
#define ROW_B   80
#define TILE_B  (128 * ROW_B)        // 10240 B
#define STAGE_B (2 * TILE_B)         // 20480 B
#define PIPE    4
#define SM_MAIN (PIPE * STAGE_B)     // 81920 B
// out-kernel B tile: [32 k][128 n] bf16, pitch 272 B (17x16B, conflict-free)
#define BROW_B   272
#define BTILE_B  (32 * BROW_B)       // 8704 B
#define OSTAGE_B (TILE_B + BTILE_B)  // 18944 B
#define SM_OUT   (PIPE * OSTAGE_B)   // 75776 B

// ---------------------------------------------------------------------------
// Stage fills
// ---------------------------------------------------------------------------
__device__ __forceinline__ void fill_gram(const bf16* __restrict__ Ag, int lda,
                                          const bf16* __restrict__ Bg, int ldb,
                                          int k0, uint32_t st,
                                          int fr, int fkB, int fkE) {
    const bf16* ga = Ag + (size_t)fr * lda + k0 + fkE;
    const bf16* gb = Bg + (size_t)fr * ldb + k0 + fkE;
    const uint32_t sa = st + fr * ROW_B + fkB;
    const uint32_t sb = st + TILE_B + fr * ROW_B + fkB;
    cpasync16(sa, ga);
    cpasync16(sa + 64 * ROW_B, ga + (size_t)64 * lda);
    cpasync16(sb, gb);
    cpasync16(sb + 64 * ROW_B, gb + (size_t)64 * ldb);
}

__device__ __forceinline__ void fill_tb(const bf16* __restrict__ Ag, int lda,
                                        const bf16* __restrict__ Bg, int ldb,
                                        int k0, uint32_t st,
                                        int fr, int fkB, int fkE,
                                        int br0, int bc0) {
    const bf16* ga = Ag + (size_t)fr * lda + k0 + fkE;
    const uint32_t sa = st + fr * ROW_B + fkB;
    cpasync16(sa, ga);
    cpasync16(sa + 64 * ROW_B, ga + (size_t)64 * lda);
    const uint32_t sbb = st + TILE_B;
    cpasync16(sbb + br0 * BROW_B + bc0 * 16,
              Bg + (size_t)(k0 + br0) * ldb + bc0 * 8);
    cpasync16(sbb + (br0 + 16) * BROW_B + bc0 * 16,
              Bg + (size_t)(k0 + br0 + 16) * ldb + bc0 * 8);
}

// ---------------------------------------------------------------------------
// Compute one 32-k stage.
// ---------------------------------------------------------------------------
__device__ __forceinline__ void compute_stage(uint32_t Abase, uint32_t Bbase,
                                              int mw0, int nw0, int lA_row, int lA_k,
                                              int lB_row, int lB_k,
                                              float acc[4][4][4]) {
    #pragma unroll
    for (int ks = 0; ks < 2; ks++) {
        uint32_t afr[4][4], bfr[4][2];
        #pragma unroll
        for (int i = 0; i < 4; i++)
            ldm_x4(afr[i], Abase + (mw0 + i * 16 + lA_row) * ROW_B
                                 + (ks * 16 + lA_k) * 2);
        #pragma unroll
        for (int p = 0; p < 2; p++) {
            uint32_t r[4];
            ldm_x4(r, Bbase + (nw0 + p * 16 + lB_row) * ROW_B
                            + (ks * 16 + lB_k) * 2);
            bfr[p * 2][0] = r[0]; bfr[p * 2][1] = r[1];
            bfr[p * 2 + 1][0] = r[2]; bfr[p * 2 + 1][1] = r[3];
        }
        #pragma unroll
        for (int i = 0; i < 4; i++)
            #pragma unroll
            for (int j = 0; j < 4; j++)
                mma16816(acc[i][j], afr[i], bfr[j]);
    }
}

__device__ __forceinline__ void compute_stage_tb(uint32_t Abase, uint32_t Bbase,
                                                 int mw0, int nw0, int lA_row, int lA_k,
                                                 int q, int l,
                                                 float acc[4][4][4]) {
    #pragma unroll
    for (int ks = 0; ks < 2; ks++) {
        uint32_t afr[4][4], bfr[4][2];
        #pragma unroll
        for (int i = 0; i < 4; i++)
            ldm_x4(afr[i], Abase + (mw0 + i * 16 + lA_row) * ROW_B
                                 + (ks * 16 + lA_k) * 2);
        #pragma unroll
        for (int p = 0; p < 2; p++) {
            uint32_t r[4];
            ldm_x4t(r, Bbase + (ks * 16 + (q & 1) * 8 + (l & 7)) * BROW_B
                             + (nw0 + p * 16 + (q >> 1) * 8) * 2);
            bfr[p * 2][0] = r[0]; bfr[p * 2][1] = r[1];
            bfr[p * 2 + 1][0] = r[2]; bfr[p * 2 + 1][1] = r[3];
        }
        #pragma unroll
        for (int i = 0; i < 4; i++)
            #pragma unroll
            for (int j = 0; j < 4; j++)
                mma16816(acc[i][j], afr[i], bfr[j]);
    }
}

// ---------------------------------------------------------------------------
// Kernel 1: fused norms + bf16 conversion.
// ---------------------------------------------------------------------------
__global__ __launch_bounds__(256) void normconv_kernel(const float* __restrict__ x1,
                                                       const float* __restrict__ x2) {
    const int row = blockIdx.x;                     // b*CH + c
    const int t = threadIdx.x;
    const size_t base = (size_t)row * NPIX;
    float4 va[4], vb[4];
    float s1 = 0.f, s2 = 0.f;
    #pragma unroll
    for (int p = 0; p < 4; p++) {
        va[p] = *(const float4*)(x1 + base + (size_t)(p * 256 + t) * 4);
        vb[p] = *(const float4*)(x2 + base + (size_t)(p * 256 + t) * 4);
        s1 += va[p].x * va[p].x + va[p].y * va[p].y + va[p].z * va[p].z + va[p].w * va[p].w;
        s2 += vb[p].x * vb[p].x + vb[p].y * vb[p].y + vb[p].z * vb[p].z + vb[p].w * vb[p].w;
    }
    __shared__ float sh1[8], sh2[8];
    const int lane = t & 31, w = t >> 5;
    #pragma unroll
    for (int o = 16; o; o >>= 1) {
        s1 += __shfl_xor_sync(0xffffffffu, s1, o);
        s2 += __shfl_xor_sync(0xffffffffu, s2, o);
    }
    if (lane == 0) { sh1[w] = s1; sh2[w] = s2; }
    __syncthreads();
    float t1 = 0.f, t2 = 0.f;
    #pragma unroll
    for (int i = 0; i < 8; i++) { t1 += sh1[i]; t2 += sh2[i]; }
    const float i1 = 1.f / fmaxf(sqrtf(t1), 1e-12f);
    const float i2 = 1.f / fmaxf(sqrtf(t2), 1e-12f);
    if (t == 0) { g_inv1[row] = i1; g_inv2[row] = i2; }

    #pragma unroll
    for (int p = 0; p < 4; p++) {
        const size_t off = base + (size_t)(p * 256 + t) * 4;
        const float a[4]  = {va[p].x, va[p].y, va[p].z, va[p].w};
        const float bb[4] = {vb[p].x, vb[p].y, vb[p].z, vb[p].w};
        bf16 sv[4], r1v[4], r2v[4];
        #pragma unroll
        for (int i = 0; i < 4; i++) {
            sv[i]  = __float2bfloat16(i1 * a[i] + i2 * bb[i]);
            r1v[i] = __float2bfloat16(a[i]);
            r2v[i] = __float2bfloat16(bb[i]);
        }
        *(uint2*)(g_s  + off) = *(const uint2*)sv;
        *(uint2*)(g_r1 + off) = *(const uint2*)r1v;
        *(uint2*)(g_r2 + off) = *(const uint2*)r2v;
    }
}

// ---------------------------------------------------------------------------
// Kernel 2: gram HMMA, split-K=2, single-sync 4-stage pipeline.
// grid (2 dblk, 2 cblk, B*4): z = b*4 + mat*2 + ks.
// ---------------------------------------------------------------------------
__global__ __launch_bounds__(256, 2) void gram_mma() {
    extern __shared__ char sm[];
    const uint32_t smb = smem_u32(sm);
    const int t = threadIdx.x, w = t >> 5, l = t & 31;
    const int dblk = blockIdx.x, cblk = blockIdx.y;
    const int zi = blockIdx.z;
    const int b = zi >> 2, mat = (zi >> 1) & 1, ks = zi & 1;

    const bf16* Ag = g_s + (size_t)b * CN + (size_t)(cblk * 128) * NPIX + ks * 2048;
    const bf16* Bg = (mat ? g_r2 : g_r1) + (size_t)b * CN
                   + (size_t)(dblk * 128) * NPIX + ks * 2048;

    const int mw0 = (w >> 2) * 64, nw0 = (w & 3) * 32;
    const int fr  = t >> 2;
    const int fkB = (t & 3) * 16;
    const int fkE = (t & 3) * 8;
    const int lA_row = l & 15, lA_k = (l >> 4) * 8;
    const int q = l >> 3;
    const int lB_row = ((q >> 1) * 8) + (l & 7);
    const int lB_k = (q & 1) * 8;

    float acc[4][4][4] = {};
    const int niter = 2048 / 32;     // 64

    #pragma unroll
    for (int s = 0; s < PIPE - 1; s++) {
        fill_gram(Ag, NPIX, Bg, NPIX, s * 32, smb + s * STAGE_B, fr, fkB, fkE);
        CP_COMMIT();
    }
    #pragma unroll 1
    for (int it = 0; it < niter; it++) {
        CP_WAIT(PIPE - 2);
        __syncthreads();
        if (it + PIPE - 1 < niter)
            fill_gram(Ag, NPIX, Bg, NPIX, (it + PIPE - 1) * 32,
                      smb + ((it + PIPE - 1) & (PIPE - 1)) * STAGE_B, fr, fkB, fkE);
        CP_COMMIT();
        const uint32_t Abase = smb + (it & (PIPE - 1)) * STAGE_B;
        compute_stage(Abase, Abase + TILE_B, mw0, nw0, lA_row, lA_k, lB_row, lB_k, acc);
    }

    float* S = g_Sp[mat * 2 + ks] + (size_t)(b * CH + cblk * 128) * CH + dblk * 128;
    const int rr = l >> 2, cc = (l & 3) * 2;
    #pragma unroll
    for (int i = 0; i < 4; i++)
        #pragma unroll
        for (int j = 0; j < 4; j++) {
            const int c_ = mw0 + i * 16 + rr;
            const int d_ = nw0 + j * 8 + cc;
            float2 lo = {acc[i][j][0], acc[i][j][1]};
            float2 hi = {acc[i][j][2], acc[i][j][3]};
            *(float2*)&S[(size_t)c_ * CH + d_] = lo;
            *(float2*)&S[(size_t)(c_ + 8) * CH + d_] = hi;
        }
}

// ---------------------------------------------------------------------------
// Kernel 3: warp-per-row softmax. 8 rows per 256-thread CTA, no __syncthreads.
// grid = B*CH/8 = 512 blocks.
// ---------------------------------------------------------------------------
__global__ __launch_bounds__(256) void softmax_kernel() {
    const int wid = threadIdx.x >> 5, lane = threadIdx.x & 31;
    const int row = blockIdx.x * 8 + wid;          // b*CH + c
    const size_t base = (size_t)row * CH + lane * 8;
    const int invb = (row >> 8) << 8;              // b*CH
    const int d0 = lane * 8;

    float v1[8], v2[8];
    {
        const float4 p0a = *(const float4*)&g_Sp[0][base];
        const float4 p0b = *(const float4*)&g_Sp[0][base + 4];
        const float4 p1a = *(const float4*)&g_Sp[1][base];
        const float4 p1b = *(const float4*)&g_Sp[1][base + 4];
        const float4 p2a = *(const float4*)&g_Sp[2][base];
        const float4 p2b = *(const float4*)&g_Sp[2][base + 4];
        const float4 p3a = *(const float4*)&g_Sp[3][base];
        const float4 p3b = *(const float4*)&g_Sp[3][base + 4];
        const float4 i1a = *(const float4*)&g_inv1[invb + d0];
        const float4 i1b = *(const float4*)&g_inv1[invb + d0 + 4];
        const float4 i2a = *(const float4*)&g_inv2[invb + d0];
        const float4 i2b = *(const float4*)&g_inv2[invb + d0 + 4];
        const float* q0a = (const float*)&p0a; const float* q0b = (const float*)&p0b;
        const float* q1a = (const float*)&p1a; const float* q1b = (const float*)&p1b;
        const float* q2a = (const float*)&p2a; const float* q2b = (const float*)&p2b;
        const float* q3a = (const float*)&p3a; const float* q3b = (const float*)&p3b;
        const float* j1a = (const float*)&i1a; const float* j1b = (const float*)&i1b;
        const float* j2a = (const float*)&i2a; const float* j2b = (const float*)&i2b;
        #pragma unroll
        for (int i = 0; i < 4; i++) {
            v1[i]     = (q0a[i] + q1a[i]) * j1a[i];
            v1[i + 4] = (q0b[i] + q1b[i]) * j1b[i];
            v2[i]     = (q2a[i] + q3a[i]) * j2a[i];
            v2[i + 4] = (q2b[i] + q3b[i]) * j2b[i];
        }
    }

    float m1 = v1[0], m2 = v2[0];
    #pragma unroll
    for (int i = 1; i < 8; i++) { m1 = fmaxf(m1, v1[i]); m2 = fmaxf(m2, v2[i]); }
    #pragma unroll
    for (int o = 16; o; o >>= 1) {
        m1 = fmaxf(m1, __shfl_xor_sync(0xffffffffu, m1, o));
        m2 = fmaxf(m2, __shfl_xor_sync(0xffffffffu, m2, o));
    }
    float s1 = 0.f, s2 = 0.f;
    #pragma unroll
    for (int i = 0; i < 8; i++) {
        v1[i] = __expf(v1[i] - m1); s1 += v1[i];
        v2[i] = __expf(v2[i] - m2); s2 += v2[i];
    }
    #pragma unroll
    for (int o = 16; o; o >>= 1) {
        s1 += __shfl_xor_sync(0xffffffffu, s1, o);
        s2 += __shfl_xor_sync(0xffffffffu, s2, o);
    }
    const float r1 = 1.f / s1, r2 = 1.f / s2;
    uint32_t o1[4], o2[4];
    #pragma unroll
    for (int i = 0; i < 4; i++) {
        __nv_bfloat162 h1 = __floats2bfloat162_rn(v1[2 * i] * r1, v1[2 * i + 1] * r1);
        __nv_bfloat162 h2 = __floats2bfloat162_rn(v2[2 * i] * r2, v2[2 * i + 1] * r2);
        o1[i] = *(const uint32_t*)&h1;
        o2[i] = *(const uint32_t*)&h2;
    }
    *(uint4*)(g_A1 + base) = *(const uint4*)o1;
    *(uint4*)(g_A2 + base) = *(const uint4*)o2;
}

// ---------------------------------------------------------------------------
// Kernel 4: back-projection HMMA (trans-B), fused 16-iter single-sync loop.
// Single-pass epilogue: full 128x128 Z staged in smem (67.6 KB <= 75.8 KB).
// grid (2 cblk, 32 nblk, B).
// ---------------------------------------------------------------------------
#define ZPITCH 132

__global__ __launch_bounds__(256, 2) void out_mma(const float* __restrict__ x1,
                                                  const float* __restrict__ x2,
                                                  float* __restrict__ out) {
    extern __shared__ char sm[];
    const uint32_t smb = smem_u32(sm);
    const int t = threadIdx.x, w = t >> 5, l = t & 31;
    const int cblk = blockIdx.x, nblk = blockIdx.y, b = blockIdx.z;
    const int n0 = nblk * 128, c0 = cblk * 128;

    const bf16* Apt[2] = { g_A1 + (size_t)(b * CH + c0) * CH,
                           g_A2 + (size_t)(b * CH + c0) * CH };
    const bf16* Bpt[2] = { g_r1 + (size_t)b * CN + n0,
                           g_r2 + (size_t)b * CN + n0 };

    const int mw0 = (w >> 2) * 64, nw0 = (w & 3) * 32;
    const int fr  = t >> 2;
    const int fkB = (t & 3) * 16;
    const int fkE = (t & 3) * 8;
    const int lA_row = l & 15, lA_k = (l >> 4) * 8;
    const int q = l >> 3;
    const int br0 = t >> 4, bc0 = t & 15;

    float acc[4][4][4] = {};
    const int niter = 16;            // 2 mats x 8 k-chunks

    #pragma unroll
    for (int s = 0; s < PIPE - 1; s++) {
        fill_tb(Apt[s >> 3], CH, Bpt[s >> 3], NPIX, (s & 7) * 32,
                smb + s * OSTAGE_B, fr, fkB, fkE, br0, bc0);
        CP_COMMIT();
    }
    #pragma unroll 1
    for (int it = 0; it < niter; it++) {
        CP_WAIT(PIPE - 2);
        __syncthreads();
        if (it + PIPE - 1 < niter) {
            const int nx = it + PIPE - 1;
            fill_tb(Apt[nx >> 3], CH, Bpt[nx >> 3], NPIX, (nx & 7) * 32,
                    smb + (nx & (PIPE - 1)) * OSTAGE_B, fr, fkB, fkE, br0, bc0);
        }
        CP_COMMIT();
        const uint32_t Abase = smb + (it & (PIPE - 1)) * OSTAGE_B;
        compute_stage_tb(Abase, Abase + TILE_B, mw0, nw0, lA_row, lA_k, q, l, acc);
    }
    __syncthreads();

    // single-pass epilogue: stage full Z [128 n][ZPITCH c]
    const int rr = l >> 2, cc = (l & 3) * 2;
    float* Zs = (float*)sm;
    #pragma unroll
    for (int i = 0; i < 4; i++)
        #pragma unroll
        for (int j = 0; j < 4; j++) {
            const int cl = mw0 + i * 16 + rr;
            const int nl = nw0 + j * 8 + cc;
            Zs[(size_t)nl * ZPITCH + cl]           = acc[i][j][0];
            Zs[(size_t)(nl + 1) * ZPITCH + cl]     = acc[i][j][1];
            Zs[(size_t)nl * ZPITCH + cl + 8]       = acc[i][j][2];
            Zs[(size_t)(nl + 1) * ZPITCH + cl + 8] = acc[i][j][3];
        }
    __syncthreads();
    #pragma unroll
    for (int p = 0; p < 16; p++) {
        const int idx = t + p * 256;
        const int n = idx >> 5, c4 = (idx & 31) * 4;
        const float4 z = *(const float4*)&Zs[(size_t)n * ZPITCH + c4];
        const size_t g = (size_t)b * CN + (size_t)(n0 + n) * CH + c0 + c4;
        const float4 a = *(const float4*)(x1 + g);
        const float4 bb = *(const float4*)(x2 + g);
        float4 o;
        o.x = z.x + a.x + bb.x; o.y = z.y + a.y + bb.y;
        o.z = z.z + a.z + bb.z; o.w = z.w + a.w + bb.w;
        *(float4*)(out + g) = o;
    }
}

// ---------------------------------------------------------------------------
extern "C" void kernel_launch(void* const* d_in, const int* in_sizes, int n_in,
                              void* d_out, int out_size) {
    (void)in_sizes; (void)n_in; (void)out_size;
    const float* x1 = (const float*)d_in[0];
    const float* x2 = (const float*)d_in[1];
    float* out = (float*)d_out;

    cudaFuncSetAttribute(gram_mma, cudaFuncAttributeMaxDynamicSharedMemorySize, SM_MAIN);
    cudaFuncSetAttribute(out_mma,  cudaFuncAttributeMaxDynamicSharedMemorySize, SM_OUT);

    normconv_kernel<<<BATCH * CH, 256>>>(x1, x2);
    gram_mma<<<dim3(2, 2, BATCH * 4), 256, SM_MAIN>>>();
    softmax_kernel<<<BATCH * CH / 8, 256>>>();
    out_mma<<<dim3(2, 32, BATCH), 256, SM_OUT>>>(x1, x2, out);
}